// round 1
// baseline (speedup 1.0000x reference)
#include <cuda_runtime.h>
#include <math.h>

// Problem constants
#define B_   256
#define T_   500
#define M_   512
#define L_   128
#define NROWS (B_ * T_)   // 128000
#define N_   256          // 2*L (V cols then U cols)

// GEMM tile
#define BM 64
#define BN 256
#define BK 16

// ---------------------------------------------------------------------------
// Phase 1: fused  C = H @ [Wv;Wu]^T  -> tanh/sigmoid -> dot with Ww -> A_pre
// One block computes a 64-row x 256-col tile (all columns), then reduces the
// gated product per row entirely in registers/shuffles.
// ---------------------------------------------------------------------------
__global__ __launch_bounds__(256, 2)
void mil_phase1(const float* __restrict__ H,
                const float* __restrict__ Wv, const float* __restrict__ bv,
                const float* __restrict__ Wu, const float* __restrict__ bu,
                const float* __restrict__ Ww, const float* __restrict__ bw,
                float* __restrict__ A_pre)
{
    __shared__ float Hs[BK][BM];   // transposed: Hs[k][row]
    __shared__ float Ws[BK][BN];   // transposed: Ws[k][col]

    const int tid = threadIdx.x;
    const int tx  = tid & 31;      // 32 column-groups of 8
    const int ty  = tid >> 5;      // 8 row-groups of 8
    const int row0 = blockIdx.x * BM;

    float acc[8][8];
#pragma unroll
    for (int r = 0; r < 8; ++r)
#pragma unroll
        for (int c = 0; c < 8; ++c) acc[r][c] = 0.f;

    // load mappings
    const int h_row = tid >> 2;    // 0..63
    const int h_kq  = tid & 3;     // which float4 of the 16-wide K slice
    const float* wsrc = (tid < L_) ? &Wv[(size_t)tid * M_]
                                   : &Wu[(size_t)(tid - L_) * M_];

    for (int k0 = 0; k0 < M_; k0 += BK) {
        // H tile: 64 rows x 16 k (each thread: one float4, stores transposed)
        {
            const float4 v = *reinterpret_cast<const float4*>(
                &H[(size_t)(row0 + h_row) * M_ + k0 + h_kq * 4]);
            Hs[h_kq * 4 + 0][h_row] = v.x;
            Hs[h_kq * 4 + 1][h_row] = v.y;
            Hs[h_kq * 4 + 2][h_row] = v.z;
            Hs[h_kq * 4 + 3][h_row] = v.w;
        }
        // W tile: 256 rows x 16 k (each thread owns row 'tid', 4 float4s)
#pragma unroll
        for (int i = 0; i < 4; ++i) {
            const float4 v = *reinterpret_cast<const float4*>(&wsrc[k0 + i * 4]);
            Ws[i * 4 + 0][tid] = v.x;
            Ws[i * 4 + 1][tid] = v.y;
            Ws[i * 4 + 2][tid] = v.z;
            Ws[i * 4 + 3][tid] = v.w;
        }
        __syncthreads();

#pragma unroll
        for (int k = 0; k < BK; ++k) {
            float a[8], b[8];
            float4 a0 = *reinterpret_cast<const float4*>(&Hs[k][ty * 8]);
            float4 a1 = *reinterpret_cast<const float4*>(&Hs[k][ty * 8 + 4]);
            float4 b0 = *reinterpret_cast<const float4*>(&Ws[k][tx * 8]);
            float4 b1 = *reinterpret_cast<const float4*>(&Ws[k][tx * 8 + 4]);
            a[0]=a0.x; a[1]=a0.y; a[2]=a0.z; a[3]=a0.w;
            a[4]=a1.x; a[5]=a1.y; a[6]=a1.z; a[7]=a1.w;
            b[0]=b0.x; b[1]=b0.y; b[2]=b0.z; b[3]=b0.w;
            b[4]=b1.x; b[5]=b1.y; b[6]=b1.z; b[7]=b1.w;
#pragma unroll
            for (int r = 0; r < 8; ++r)
#pragma unroll
                for (int c = 0; c < 8; ++c)
                    acc[r][c] = fmaf(a[r], b[c], acc[r][c]);
        }
        __syncthreads();
    }

    // ---- Epilogue: activation + gated reduce ----
    // cols of this thread: j = tx*8+c.  tx<16 -> V column l=j ; tx>=16 -> U
    // column l = j-128.  Partner thread tx^16 holds the matching other half
    // for the SAME l values, so one shfl pairs V and U.
    const int  colbase = tx * 8;
    const bool isV = (colbase < L_);
    float bias[8], wmul[8];
#pragma unroll
    for (int c = 0; c < 8; ++c) {
        int j = colbase + c;
        if (isV) { bias[c] = bv[j];       wmul[c] = Ww[j]; }
        else     { bias[c] = bu[j - L_];  wmul[c] = 1.f;   }
    }
    const float bw0 = bw[0];

    float srow[8];
#pragma unroll
    for (int r = 0; r < 8; ++r) srow[r] = 0.f;

#pragma unroll
    for (int r = 0; r < 8; ++r) {
#pragma unroll
        for (int c = 0; c < 8; ++c) {
            float x  = acc[r][c] + bias[c];
            float tv = tanhf(x) * wmul[c];            // V path (× Ww)
            float sv = 1.f / (1.f + expf(-x));        // U path
            float val = isV ? tv : sv;                // predicated, no divergence
            float partner = __shfl_xor_sync(0xffffffffu, val, 16);
            srow[r] += val * partner;                 // = V(l)*Ww(l)*U(l)
        }
    }
    // reduce over the 16 lanes of each half (both halves hold identical sums)
#pragma unroll
    for (int r = 0; r < 8; ++r) {
        srow[r] += __shfl_xor_sync(0xffffffffu, srow[r], 8);
        srow[r] += __shfl_xor_sync(0xffffffffu, srow[r], 4);
        srow[r] += __shfl_xor_sync(0xffffffffu, srow[r], 2);
        srow[r] += __shfl_xor_sync(0xffffffffu, srow[r], 1);
    }
    if (tx == 0) {
#pragma unroll
        for (int r = 0; r < 8; ++r)
            A_pre[(size_t)(row0 + ty * 8 + r)] = srow[r] + bw0;
    }
}

// ---------------------------------------------------------------------------
// Phase 2: softmax over T per bag. Writes A_sftmx.
// ---------------------------------------------------------------------------
__global__ __launch_bounds__(256)
void mil_softmax(const float* __restrict__ A_pre, float* __restrict__ Asm)
{
    __shared__ float sh[256];
    const int b   = blockIdx.x;
    const int tid = threadIdx.x;
    const float* src = A_pre + (size_t)b * T_;

    const int t0 = tid, t1 = tid + 256;
    float v0 = src[t0];
    float v1 = (t1 < T_) ? src[t1] : -INFINITY;

    // block max
    sh[tid] = fmaxf(v0, v1);
    __syncthreads();
    for (int s = 128; s > 0; s >>= 1) {
        if (tid < s) sh[tid] = fmaxf(sh[tid], sh[tid + s]);
        __syncthreads();
    }
    const float mx = sh[0];
    __syncthreads();

    float e0 = expf(v0 - mx);
    float e1 = (t1 < T_) ? expf(v1 - mx) : 0.f;
    sh[tid] = e0 + e1;
    __syncthreads();
    for (int s = 128; s > 0; s >>= 1) {
        if (tid < s) sh[tid] += sh[tid + s];
        __syncthreads();
    }
    const float inv = 1.f / sh[0];

    Asm[(size_t)b * T_ + t0] = e0 * inv;
    if (t1 < T_) Asm[(size_t)b * T_ + t1] = e1 * inv;
}

// ---------------------------------------------------------------------------
// Phase 3: Mfeat[b,m] = sum_t a[b,t]*H[b,t,m];  out = Mfeat@Wc^T + bc*bias_rel
// One block per bag, thread == feature m (512 == M). Fully coalesced H reads.
// ---------------------------------------------------------------------------
__global__ __launch_bounds__(512)
void mil_phase3(const float* __restrict__ H,
                const float* __restrict__ a,
                const float* __restrict__ Wc, const float* __restrict__ bc,
                float* __restrict__ out)
{
    __shared__ float a_s[T_];
    __shared__ float red[512];
    const int b = blockIdx.x;
    const int m = threadIdx.x;

    for (int t = m; t < T_; t += 512) a_s[t] = a[(size_t)b * T_ + t];
    __syncthreads();

    // bias_rel = sum(a)  (== 1 up to fp, computed like the reference)
    red[m] = (m < T_) ? a_s[m] : 0.f;
    __syncthreads();
    for (int s = 256; s > 0; s >>= 1) {
        if (m < s) red[m] += red[m + s];
        __syncthreads();
    }
    const float bias_rel = red[0];
    __syncthreads();

    // weighted feature sum over T
    const float* Hb = H + (size_t)b * T_ * M_ + m;
    float mf = 0.f;
#pragma unroll 4
    for (int t = 0; t < T_; ++t) mf = fmaf(a_s[t], Hb[(size_t)t * M_], mf);

    // project to 2 outputs via block reductions
    float p0 = mf * Wc[m];
    float p1 = mf * Wc[M_ + m];

    red[m] = p0;
    __syncthreads();
    for (int s = 256; s > 0; s >>= 1) {
        if (m < s) red[m] += red[m + s];
        __syncthreads();
    }
    const float o0 = red[0];
    __syncthreads();

    red[m] = p1;
    __syncthreads();
    for (int s = 256; s > 0; s >>= 1) {
        if (m < s) red[m] += red[m + s];
        __syncthreads();
    }
    if (m == 0) {
        out[(size_t)b * 2 + 0] = o0     + bc[0] * bias_rel;
        out[(size_t)b * 2 + 1] = red[0] + bc[1] * bias_rel;
    }
}

// ---------------------------------------------------------------------------
// Launch: outputs packed as (out[256,2], A_sftmx[256,500], A_pre[256,1,500]).
// A_pre is written by phase1 directly into the output buffer; phase2/3 read
// back from d_out regions -> no scratch memory needed.
// ---------------------------------------------------------------------------
extern "C" void kernel_launch(void* const* d_in, const int* in_sizes, int n_in,
                              void* d_out, int out_size)
{
    const float* H  = (const float*)d_in[0];
    const float* Wv = (const float*)d_in[1];
    const float* bv = (const float*)d_in[2];
    const float* Wu = (const float*)d_in[3];
    const float* bu = (const float*)d_in[4];
    const float* Ww = (const float*)d_in[5];
    const float* bw = (const float*)d_in[6];
    const float* Wc = (const float*)d_in[7];
    const float* bc = (const float*)d_in[8];

    float* out   = (float*)d_out;               // [256,2]
    float* A_sm  = out + (size_t)B_ * 2;        // [256,500]
    float* A_pre = A_sm + (size_t)B_ * T_;      // [256,1,500]

    mil_phase1<<<NROWS / BM, 256>>>(H, Wv, bv, Wu, bu, Ww, bw, A_pre);
    mil_softmax<<<B_, 256>>>(A_pre, A_sm);
    mil_phase3<<<B_, 512>>>(H, A_sm, Wc, bc, out);
}

// round 2
// speedup vs baseline: 1.2030x; 1.2030x over previous
#include <cuda_runtime.h>
#include <math.h>

// Problem constants
#define B_   256
#define T_   500
#define M_   512
#define L_   128
#define NROWS (B_ * T_)   // 128000

// GEMM tile (phase 1)
#define BM 128
#define BN 256
#define BK 16
#define NTHR 512

// ---------------------------------------------------------------------------
// Phase 1: fused  C = H @ [Wv;Wu]^T  -> tanh/sigmoid -> dot with Ww -> A_pre
// Block: 128 rows x 256 cols (all cols). 512 threads, 8x8 per-thread tile.
// Double-buffered smem, register-prefetched global loads, 1 sync / k-tile.
// ---------------------------------------------------------------------------
__global__ __launch_bounds__(NTHR, 1)
void mil_phase1(const float* __restrict__ H,
                const float* __restrict__ Wv, const float* __restrict__ bv,
                const float* __restrict__ Wu, const float* __restrict__ bu,
                const float* __restrict__ Ww, const float* __restrict__ bw,
                float* __restrict__ A_pre)
{
    __shared__ float Hs[2][BK][BM];   // k-major: Hs[buf][k][row]   16 KB
    __shared__ float Ws[2][BK][BN];   // k-major: Ws[buf][k][col]   32 KB

    const int tid = threadIdx.x;
    const int cx  = tid & 31;      // 32 col-groups of 8 (lane id)
    const int ry  = tid >> 5;      // 16 row-groups of 8 (warp id)
    const int row0 = blockIdx.x * BM;

    float acc[8][8];
#pragma unroll
    for (int r = 0; r < 8; ++r)
#pragma unroll
        for (int c = 0; c < 8; ++c) acc[r][c] = 0.f;

    // ---- load mappings ----
    // A: 128 rows x 16 k = 512 float4; one per thread
    const int a_row = tid >> 2;          // 0..127
    const int a_q   = tid & 3;           // float4 index within 16-wide K
    const float* gA = &H[(size_t)(row0 + a_row) * M_ + a_q * 4];
    // B: 256 rows x 16 k = 1024 float4; two per thread
    const int w_row = tid >> 1;          // 0..255
    const int w_q   = tid & 1;           // covers q = w_q and w_q+2
    const float* gB = (w_row < L_) ? &Wv[(size_t)w_row * M_]
                                   : &Wu[(size_t)(w_row - L_) * M_];

    // ---- prologue: tile 0 into buffer 0 ----
    {
        const float4 va = *reinterpret_cast<const float4*>(gA);
        Hs[0][a_q * 4 + 0][a_row] = va.x;
        Hs[0][a_q * 4 + 1][a_row] = va.y;
        Hs[0][a_q * 4 + 2][a_row] = va.z;
        Hs[0][a_q * 4 + 3][a_row] = va.w;
#pragma unroll
        for (int i = 0; i < 2; ++i) {
            const int q = w_q + 2 * i;
            const float4 vb = *reinterpret_cast<const float4*>(&gB[q * 4]);
            Ws[0][q * 4 + 0][w_row] = vb.x;
            Ws[0][q * 4 + 1][w_row] = vb.y;
            Ws[0][q * 4 + 2][w_row] = vb.z;
            Ws[0][q * 4 + 3][w_row] = vb.w;
        }
    }
    __syncthreads();

    const int NKT = M_ / BK;   // 32
    for (int kt = 0; kt < NKT; ++kt) {
        const int cb = kt & 1;
        const int nb = cb ^ 1;

        // prefetch next tile into registers (overlaps with compute)
        float4 pa, pb0, pb1;
        if (kt + 1 < NKT) {
            const int k0n = (kt + 1) * BK;
            pa  = *reinterpret_cast<const float4*>(&gA[k0n]);
            pb0 = *reinterpret_cast<const float4*>(&gB[k0n + w_q * 4]);
            pb1 = *reinterpret_cast<const float4*>(&gB[k0n + (w_q + 2) * 4]);
        }

        // compute on current buffer
#pragma unroll
        for (int k = 0; k < BK; ++k) {
            float a[8], b[8];
            float4 a0 = *reinterpret_cast<const float4*>(&Hs[cb][k][ry * 8]);
            float4 a1 = *reinterpret_cast<const float4*>(&Hs[cb][k][ry * 8 + 4]);
            float4 b0 = *reinterpret_cast<const float4*>(&Ws[cb][k][cx * 8]);
            float4 b1 = *reinterpret_cast<const float4*>(&Ws[cb][k][cx * 8 + 4]);
            a[0]=a0.x; a[1]=a0.y; a[2]=a0.z; a[3]=a0.w;
            a[4]=a1.x; a[5]=a1.y; a[6]=a1.z; a[7]=a1.w;
            b[0]=b0.x; b[1]=b0.y; b[2]=b0.z; b[3]=b0.w;
            b[4]=b1.x; b[5]=b1.y; b[6]=b1.z; b[7]=b1.w;
#pragma unroll
            for (int r = 0; r < 8; ++r)
#pragma unroll
                for (int c = 0; c < 8; ++c)
                    acc[r][c] = fmaf(a[r], b[c], acc[r][c]);
        }

        // store prefetched tile into the other buffer
        if (kt + 1 < NKT) {
            Hs[nb][a_q * 4 + 0][a_row] = pa.x;
            Hs[nb][a_q * 4 + 1][a_row] = pa.y;
            Hs[nb][a_q * 4 + 2][a_row] = pa.z;
            Hs[nb][a_q * 4 + 3][a_row] = pa.w;
            const int q0 = w_q, q1 = w_q + 2;
            Ws[nb][q0 * 4 + 0][w_row] = pb0.x;
            Ws[nb][q0 * 4 + 1][w_row] = pb0.y;
            Ws[nb][q0 * 4 + 2][w_row] = pb0.z;
            Ws[nb][q0 * 4 + 3][w_row] = pb0.w;
            Ws[nb][q1 * 4 + 0][w_row] = pb1.x;
            Ws[nb][q1 * 4 + 1][w_row] = pb1.y;
            Ws[nb][q1 * 4 + 2][w_row] = pb1.z;
            Ws[nb][q1 * 4 + 3][w_row] = pb1.w;
        }
        __syncthreads();
    }

    // ---- Epilogue: activation + gated reduce ----
    // cols of this thread: j = cx*8+c.  cx<16 -> V column l=j ; cx>=16 -> U
    // column l = j-128.  Partner lane cx^16 holds the other half for the SAME
    // l values, so one shfl pairs V and U.
    const int  colbase = cx * 8;
    const bool isV = (colbase < L_);
    float bias[8], wmul[8];
#pragma unroll
    for (int c = 0; c < 8; ++c) {
        int j = colbase + c;
        if (isV) { bias[c] = bv[j];       wmul[c] = Ww[j]; }
        else     { bias[c] = bu[j - L_];  wmul[c] = 1.f;   }
    }
    const float bw0 = bw[0];

    float srow[8];
#pragma unroll
    for (int r = 0; r < 8; ++r) srow[r] = 0.f;

#pragma unroll
    for (int r = 0; r < 8; ++r) {
#pragma unroll
        for (int c = 0; c < 8; ++c) {
            float x  = acc[r][c] + bias[c];
            float tv = tanhf(x) * wmul[c];            // V path (x Ww)
            float sv = 1.f / (1.f + expf(-x));        // U path
            float val = isV ? tv : sv;                // predicated
            float partner = __shfl_xor_sync(0xffffffffu, val, 16);
            srow[r] += val * partner;                 // = V(l)*Ww(l)*U(l)
        }
    }
#pragma unroll
    for (int r = 0; r < 8; ++r) {
        srow[r] += __shfl_xor_sync(0xffffffffu, srow[r], 8);
        srow[r] += __shfl_xor_sync(0xffffffffu, srow[r], 4);
        srow[r] += __shfl_xor_sync(0xffffffffu, srow[r], 2);
        srow[r] += __shfl_xor_sync(0xffffffffu, srow[r], 1);
    }
    if (cx == 0) {
#pragma unroll
        for (int r = 0; r < 8; ++r)
            A_pre[(size_t)(row0 + ry * 8 + r)] = srow[r] + bw0;
    }
}

// ---------------------------------------------------------------------------
// Phase 2: softmax over T per bag. Writes A_sftmx.
// ---------------------------------------------------------------------------
__global__ __launch_bounds__(256)
void mil_softmax(const float* __restrict__ A_pre, float* __restrict__ Asm)
{
    __shared__ float sh[256];
    const int b   = blockIdx.x;
    const int tid = threadIdx.x;
    const float* src = A_pre + (size_t)b * T_;

    const int t0 = tid, t1 = tid + 256;
    float v0 = src[t0];
    float v1 = (t1 < T_) ? src[t1] : -INFINITY;

    sh[tid] = fmaxf(v0, v1);
    __syncthreads();
    for (int s = 128; s > 0; s >>= 1) {
        if (tid < s) sh[tid] = fmaxf(sh[tid], sh[tid + s]);
        __syncthreads();
    }
    const float mx = sh[0];
    __syncthreads();

    float e0 = expf(v0 - mx);
    float e1 = (t1 < T_) ? expf(v1 - mx) : 0.f;
    sh[tid] = e0 + e1;
    __syncthreads();
    for (int s = 128; s > 0; s >>= 1) {
        if (tid < s) sh[tid] += sh[tid + s];
        __syncthreads();
    }
    const float inv = 1.f / sh[0];

    Asm[(size_t)b * T_ + t0] = e0 * inv;
    if (t1 < T_) Asm[(size_t)b * T_ + t1] = e1 * inv;
}

// ---------------------------------------------------------------------------
// Phase 3: Mfeat[b,m] = sum_t a[b,t]*H[b,t,m];  out = Mfeat@Wc^T + bc*bias_rel
// ---------------------------------------------------------------------------
__global__ __launch_bounds__(512)
void mil_phase3(const float* __restrict__ H,
                const float* __restrict__ a,
                const float* __restrict__ Wc, const float* __restrict__ bc,
                float* __restrict__ out)
{
    __shared__ float a_s[T_];
    __shared__ float red[512];
    const int b = blockIdx.x;
    const int m = threadIdx.x;

    for (int t = m; t < T_; t += 512) a_s[t] = a[(size_t)b * T_ + t];
    __syncthreads();

    red[m] = (m < T_) ? a_s[m] : 0.f;
    __syncthreads();
    for (int s = 256; s > 0; s >>= 1) {
        if (m < s) red[m] += red[m + s];
        __syncthreads();
    }
    const float bias_rel = red[0];
    __syncthreads();

    const float* Hb = H + (size_t)b * T_ * M_ + m;
    float mf = 0.f;
#pragma unroll 4
    for (int t = 0; t < T_; ++t) mf = fmaf(a_s[t], Hb[(size_t)t * M_], mf);

    float p0 = mf * Wc[m];
    float p1 = mf * Wc[M_ + m];

    red[m] = p0;
    __syncthreads();
    for (int s = 256; s > 0; s >>= 1) {
        if (m < s) red[m] += red[m + s];
        __syncthreads();
    }
    const float o0 = red[0];
    __syncthreads();

    red[m] = p1;
    __syncthreads();
    for (int s = 256; s > 0; s >>= 1) {
        if (m < s) red[m] += red[m + s];
        __syncthreads();
    }
    if (m == 0) {
        out[(size_t)b * 2 + 0] = o0     + bc[0] * bias_rel;
        out[(size_t)b * 2 + 1] = red[0] + bc[1] * bias_rel;
    }
}

// ---------------------------------------------------------------------------
// Launch: outputs packed as (out[256,2], A_sftmx[256,500], A_pre[256,1,500]).
// ---------------------------------------------------------------------------
extern "C" void kernel_launch(void* const* d_in, const int* in_sizes, int n_in,
                              void* d_out, int out_size)
{
    const float* H  = (const float*)d_in[0];
    const float* Wv = (const float*)d_in[1];
    const float* bv = (const float*)d_in[2];
    const float* Wu = (const float*)d_in[3];
    const float* bu = (const float*)d_in[4];
    const float* Ww = (const float*)d_in[5];
    const float* bw = (const float*)d_in[6];
    const float* Wc = (const float*)d_in[7];
    const float* bc = (const float*)d_in[8];

    float* out   = (float*)d_out;               // [256,2]
    float* A_sm  = out + (size_t)B_ * 2;        // [256,500]
    float* A_pre = A_sm + (size_t)B_ * T_;      // [256,1,500]

    mil_phase1<<<NROWS / BM, NTHR>>>(H, Wv, bv, Wu, bu, Ww, bw, A_pre);
    mil_softmax<<<B_, 256>>>(A_pre, A_sm);
    mil_phase3<<<B_, 512>>>(H, A_sm, Wc, bc, out);
}

// round 4
// speedup vs baseline: 2.1188x; 1.7612x over previous
#include <cuda_runtime.h>
#include <cuda_bf16.h>
#include <stdint.h>
#include <math.h>

#define B_   256
#define T_   500
#define M_   512
#define L_   128
#define NROWS (B_ * T_)    // 128000

// ---- phase-1 tiling ----
#define MT   128            // rows / CTA
#define NN   256            // cols (V:0..127, U:128..255)
#define KC   64             // fp32 k per stage -> 128B bf16 rows (SW128)
#define NST  (M_ / KC)      // 8 stages
#define NTH  512

// smem: two stages of {Ahi 16K, Alo 16K, Bhi 32K, Blo 32K} = 96KB each
#define BUF   98304
#define SMEM_P1 (2 * BUF)   // 196608

// W pre-split (bf16 hi/lo), [n][k] row-major, 16B aligned
__device__ __align__(16) unsigned short g_Whi[NN * M_];
__device__ __align__(16) unsigned short g_Wlo[NN * M_];

// ===================== helpers =====================
__device__ __forceinline__ uint32_t smem_u32(const void* p) {
    uint32_t a;
    asm("{ .reg .u64 t; cvta.to.shared.u64 t, %1; cvt.u32.u64 %0, t; }"
        : "=r"(a) : "l"(p));
    return a;
}
__device__ __forceinline__ uint32_t swz(uint32_t o) { return o ^ ((o >> 3) & 0x70); }

__device__ __forceinline__ void ldsm4(uint32_t a, uint32_t& r0, uint32_t& r1,
                                      uint32_t& r2, uint32_t& r3) {
    asm volatile("ldmatrix.sync.aligned.m8n8.x4.shared.b16 {%0,%1,%2,%3}, [%4];"
                 : "=r"(r0), "=r"(r1), "=r"(r2), "=r"(r3) : "r"(a));
}
__device__ __forceinline__ void mma16816(float* c, uint32_t a0, uint32_t a1,
                                         uint32_t a2, uint32_t a3,
                                         uint32_t b0, uint32_t b1) {
    asm volatile(
        "mma.sync.aligned.m16n8k16.row.col.f32.bf16.bf16.f32 "
        "{%0,%1,%2,%3}, {%4,%5,%6,%7}, {%8,%9}, {%0,%1,%2,%3};"
        : "+f"(c[0]), "+f"(c[1]), "+f"(c[2]), "+f"(c[3])
        : "r"(a0), "r"(a1), "r"(a2), "r"(a3), "r"(b0), "r"(b1));
}
#define CP16(dst, src) \
    asm volatile("cp.async.cg.shared.global [%0], [%1], 16;" :: "r"(dst), "l"(src))
#define CP_COMMIT() asm volatile("cp.async.commit_group;" ::: "memory")
#define CP_WAIT0()  asm volatile("cp.async.wait_group 0;" ::: "memory")
#define STS128(a, x, y, z, w) \
    asm volatile("st.shared.v4.b32 [%0], {%1,%2,%3,%4};" \
                 :: "r"(a), "r"(x), "r"(y), "r"(z), "r"(w))

__device__ __forceinline__ uint32_t pack2(__nv_bfloat16 a, __nv_bfloat16 b) {
    return ((uint32_t)__bfloat16_as_ushort(b) << 16) | (uint32_t)__bfloat16_as_ushort(a);
}
__device__ __forceinline__ void split_pair(float x, float y, uint32_t& hw, uint32_t& lw) {
    __nv_bfloat16 hx = __float2bfloat16(x);
    __nv_bfloat16 hy = __float2bfloat16(y);
    __nv_bfloat16 lx = __float2bfloat16(x - __bfloat162float(hx));
    __nv_bfloat16 ly = __float2bfloat16(y - __bfloat162float(hy));
    hw = pack2(hx, hy);
    lw = pack2(lx, ly);
}

// ---------------------------------------------------------------------------
// Pre-split W = [Wv;Wu] into bf16 hi/lo (once per launch; 512KB)
// ---------------------------------------------------------------------------
__global__ void wsplit_kernel(const float* __restrict__ Wv, const float* __restrict__ Wu)
{
    int idx = blockIdx.x * 256 + threadIdx.x;          // 0 .. 131071
    int n = idx >> 9, k = idx & 511;
    float x = (n < L_) ? Wv[n * M_ + k] : Wu[(n - L_) * M_ + k];
    __nv_bfloat16 h = __float2bfloat16(x);
    __nv_bfloat16 l = __float2bfloat16(x - __bfloat162float(h));
    g_Whi[idx] = __bfloat16_as_ushort(h);
    g_Wlo[idx] = __bfloat16_as_ushort(l);
}

// ---------------------------------------------------------------------------
// Phase 1: mma.sync bf16-split GEMM + fused activation epilogue -> A_pre
// ---------------------------------------------------------------------------
__device__ __forceinline__ void load_B_async(uint32_t bufb, int kt, int tid)
{
    const int row = tid >> 1, half = tid & 1;
    const unsigned short* sh = g_Whi + row * M_ + kt * KC + half * 32;
    const unsigned short* sl = g_Wlo + row * M_ + kt * KC + half * 32;
    const uint32_t dh = bufb + 32768, dl = bufb + 65536;
#pragma unroll
    for (int j = 0; j < 4; ++j) {
        uint32_t off = swz((uint32_t)(row * 128 + (half * 4 + j) * 16));
        CP16(dh + off, sh + j * 8);
        CP16(dl + off, sl + j * 8);
    }
}

__device__ __forceinline__ void sts_A(uint32_t bufb, const float4* f, int tid)
{
    const int row = tid >> 2, q = tid & 3;
    uint32_t h0, h1, h2, h3, l0, l1, l2, l3;
    split_pair(f[0].x, f[0].y, h0, l0);
    split_pair(f[0].z, f[0].w, h1, l1);
    split_pair(f[1].x, f[1].y, h2, l2);
    split_pair(f[1].z, f[1].w, h3, l3);
    uint32_t o0 = swz((uint32_t)(row * 128 + q * 32));
    STS128(bufb + o0, h0, h1, h2, h3);
    STS128(bufb + 16384 + o0, l0, l1, l2, l3);
    split_pair(f[2].x, f[2].y, h0, l0);
    split_pair(f[2].z, f[2].w, h1, l1);
    split_pair(f[3].x, f[3].y, h2, l2);
    split_pair(f[3].z, f[3].w, h3, l3);
    uint32_t o1 = swz((uint32_t)(row * 128 + q * 32 + 16));
    STS128(bufb + o1, h0, h1, h2, h3);
    STS128(bufb + 16384 + o1, l0, l1, l2, l3);
}

#define UPAD 133   // floats per Uact row (conflict-free)

__global__ __launch_bounds__(NTH, 1)
void mil_phase1_mma(const float* __restrict__ H,
                    const float* __restrict__ bv, const float* __restrict__ bu,
                    const float* __restrict__ Ww, const float* __restrict__ bw,
                    float* __restrict__ A_pre)
{
    extern __shared__ __align__(1024) char smem[];
    const uint32_t sb = smem_u32(smem);
    const int tid  = threadIdx.x;
    const int lane = tid & 31;
    const int warp = tid >> 5;
    const int rw   = warp >> 2;      // 0..3 row group (32 rows)
    const int cw   = warp & 3;       // 0..3 col group (64 cols)
    const int row0 = blockIdx.x * MT;

    float acc[2][4][2][4];
#pragma unroll
    for (int a = 0; a < 2; ++a)
#pragma unroll
        for (int b = 0; b < 4; ++b)
#pragma unroll
            for (int c = 0; c < 2; ++c)
#pragma unroll
                for (int d = 0; d < 4; ++d) acc[a][b][c][d] = 0.f;

    const float* gA = H + (size_t)(row0 + (tid >> 2)) * M_ + (tid & 3) * 16;

    // ldmatrix per-lane address components
    const int lrow = lane & 15;
    const int lko  = (lane >> 4) * 16;
    const int arow0 = (rw * 32 + lrow) * 128;          // mt=0
    const int arow1 = (rw * 32 + 16 + lrow) * 128;     // mt=1

    // ---- prologue: stage 0 ----
    load_B_async(sb, 0, tid);
    CP_COMMIT();
    {
        float4 f[4];
#pragma unroll
        for (int i = 0; i < 4; ++i)
            f[i] = *reinterpret_cast<const float4*>(gA + i * 4);
        sts_A(sb, f, tid);
    }
    CP_WAIT0();
    __syncthreads();

    // ---- main loop ----
    for (int kt = 0; kt < NST; ++kt) {
        const uint32_t bufc = sb + (uint32_t)(kt & 1) * BUF;
        const uint32_t bufn = sb + (uint32_t)((kt + 1) & 1) * BUF;

        float4 fA[4];
        if (kt < NST - 1) {
            const float* s = gA + (kt + 1) * KC;
#pragma unroll
            for (int i = 0; i < 4; ++i)
                fA[i] = *reinterpret_cast<const float4*>(s + i * 4);
            load_B_async(bufn, kt + 1, tid);
            CP_COMMIT();
        }

        // compute stage kt: 4 k16-steps, 3 split products
#pragma unroll
        for (int ks = 0; ks < 4; ++ks) {
            const uint32_t kb = (uint32_t)(ks * 32 + lko);
            uint32_t ah[2][4], al[2][4];
            ldsm4(bufc + swz(arow0 + kb), ah[0][0], ah[0][1], ah[0][2], ah[0][3]);
            ldsm4(bufc + swz(arow1 + kb), ah[1][0], ah[1][1], ah[1][2], ah[1][3]);
            ldsm4(bufc + 16384 + swz(arow0 + kb), al[0][0], al[0][1], al[0][2], al[0][3]);
            ldsm4(bufc + 16384 + swz(arow1 + kb), al[1][0], al[1][1], al[1][2], al[1][3]);
#pragma unroll
            for (int ng = 0; ng < 4; ++ng) {
                const uint32_t bro = (uint32_t)((cw * 64 + ng * 16 + lrow) * 128) + kb;
                uint32_t bh0, bh1, bh2, bh3, bl0, bl1, bl2, bl3;
                ldsm4(bufc + 32768 + swz(bro), bh0, bh1, bh2, bh3);
                ldsm4(bufc + 65536 + swz(bro), bl0, bl1, bl2, bl3);
#pragma unroll
                for (int mt = 0; mt < 2; ++mt) {
                    // hi*hi
                    mma16816(acc[mt][ng][0], ah[mt][0], ah[mt][1], ah[mt][2], ah[mt][3], bh0, bh2);
                    mma16816(acc[mt][ng][1], ah[mt][0], ah[mt][1], ah[mt][2], ah[mt][3], bh1, bh3);
                    // hi*lo
                    mma16816(acc[mt][ng][0], ah[mt][0], ah[mt][1], ah[mt][2], ah[mt][3], bl0, bl2);
                    mma16816(acc[mt][ng][1], ah[mt][0], ah[mt][1], ah[mt][2], ah[mt][3], bl1, bl3);
                    // lo*hi
                    mma16816(acc[mt][ng][0], al[mt][0], al[mt][1], al[mt][2], al[mt][3], bh0, bh2);
                    mma16816(acc[mt][ng][1], al[mt][0], al[mt][1], al[mt][2], al[mt][3], bh1, bh3);
                }
            }
        }

        if (kt < NST - 1) {
            sts_A(bufn, fA, tid);
            CP_WAIT0();
        }
        __syncthreads();
    }

    // ---- epilogue ----
    // c-frag element (mt, ng, h, e): row = rw*32+mt*16+(lane>>2)+(e>=2?8:0)
    //                                col = cw*64+ng*16+h*8+(lane&3)*2+(e&1)
    float* Uact = reinterpret_cast<float*>(smem);              // [128][UPAD]
    float* part = reinterpret_cast<float*>(smem) + 128 * UPAD; // [2][128]

    if (cw >= 2) {   // U half: sigma(U + bu) -> Uact
#pragma unroll
        for (int mt = 0; mt < 2; ++mt)
#pragma unroll
            for (int ng = 0; ng < 4; ++ng)
#pragma unroll
                for (int h = 0; h < 2; ++h)
#pragma unroll
                    for (int e = 0; e < 4; ++e) {
                        int r  = rw * 32 + mt * 16 + (lane >> 2) + (e >= 2 ? 8 : 0);
                        int uc = (cw - 2) * 64 + ng * 16 + h * 8 + (lane & 3) * 2 + (e & 1);
                        float x = acc[mt][ng][h][e] + __ldg(&bu[uc]);
                        Uact[r * UPAD + uc] = 1.f / (1.f + expf(-x));
                    }
    }
    __syncthreads();

    if (cw < 2) {    // V half: tanh(V + bv)*Ww * Uact, row-reduce
        float srow[2][2] = {{0.f, 0.f}, {0.f, 0.f}};   // [mt][rhalf]
#pragma unroll
        for (int mt = 0; mt < 2; ++mt)
#pragma unroll
            for (int ng = 0; ng < 4; ++ng)
#pragma unroll
                for (int h = 0; h < 2; ++h)
#pragma unroll
                    for (int e = 0; e < 4; ++e) {
                        int rh = (e >= 2) ? 1 : 0;
                        int r  = rw * 32 + mt * 16 + (lane >> 2) + rh * 8;
                        int c  = cw * 64 + ng * 16 + h * 8 + (lane & 3) * 2 + (e & 1);
                        float x = acc[mt][ng][h][e] + __ldg(&bv[c]);
                        float v = tanhf(x) * __ldg(&Ww[c]);
                        srow[mt][rh] += v * Uact[r * UPAD + c];
                    }
        // reduce over lane&3 (cols only vary)
#pragma unroll
        for (int mt = 0; mt < 2; ++mt)
#pragma unroll
            for (int rh = 0; rh < 2; ++rh) {
                srow[mt][rh] += __shfl_xor_sync(0xffffffffu, srow[mt][rh], 1);
                srow[mt][rh] += __shfl_xor_sync(0xffffffffu, srow[mt][rh], 2);
            }
        if ((lane & 3) == 0) {
#pragma unroll
            for (int mt = 0; mt < 2; ++mt)
#pragma unroll
                for (int rh = 0; rh < 2; ++rh) {
                    int r = rw * 32 + mt * 16 + (lane >> 2) + rh * 8;
                    part[cw * 128 + r] = srow[mt][rh];
                }
        }
    }
    __syncthreads();

    if (tid < MT)
        A_pre[(size_t)(row0 + tid)] = part[tid] + part[128 + tid] + bw[0];
}

// ---------------------------------------------------------------------------
// Phase 2: softmax over T per bag.
// ---------------------------------------------------------------------------
__global__ __launch_bounds__(256)
void mil_softmax(const float* __restrict__ A_pre, float* __restrict__ Asm)
{
    __shared__ float sh[256];
    const int b   = blockIdx.x;
    const int tid = threadIdx.x;
    const float* src = A_pre + (size_t)b * T_;

    const int t0 = tid, t1 = tid + 256;
    float v0 = src[t0];
    float v1 = (t1 < T_) ? src[t1] : -INFINITY;

    sh[tid] = fmaxf(v0, v1);
    __syncthreads();
    for (int s = 128; s > 0; s >>= 1) {
        if (tid < s) sh[tid] = fmaxf(sh[tid], sh[tid + s]);
        __syncthreads();
    }
    const float mx = sh[0];
    __syncthreads();

    float e0 = expf(v0 - mx);
    float e1 = (t1 < T_) ? expf(v1 - mx) : 0.f;
    sh[tid] = e0 + e1;
    __syncthreads();
    for (int s = 128; s > 0; s >>= 1) {
        if (tid < s) sh[tid] += sh[tid + s];
        __syncthreads();
    }
    const float inv = 1.f / sh[0];

    Asm[(size_t)b * T_ + t0] = e0 * inv;
    if (t1 < T_) Asm[(size_t)b * T_ + t1] = e1 * inv;
}

// ---------------------------------------------------------------------------
// Phase 3: Mfeat[b,m] = sum_t a[b,t]*H[b,t,m]; out = Mfeat@Wc^T + bc*bias_rel
// ---------------------------------------------------------------------------
__global__ __launch_bounds__(512)
void mil_phase3(const float* __restrict__ H,
                const float* __restrict__ a,
                const float* __restrict__ Wc, const float* __restrict__ bc,
                float* __restrict__ out)
{
    __shared__ float a_s[T_];
    __shared__ float red[512];
    const int b = blockIdx.x;
    const int m = threadIdx.x;

    for (int t = m; t < T_; t += 512) a_s[t] = a[(size_t)b * T_ + t];
    __syncthreads();

    red[m] = (m < T_) ? a_s[m] : 0.f;
    __syncthreads();
    for (int s = 256; s > 0; s >>= 1) {
        if (m < s) red[m] += red[m + s];
        __syncthreads();
    }
    const float bias_rel = red[0];
    __syncthreads();

    const float* Hb = H + (size_t)b * T_ * M_ + m;
    float mf = 0.f;
#pragma unroll 4
    for (int t = 0; t < T_; ++t) mf = fmaf(a_s[t], Hb[(size_t)t * M_], mf);

    float p0 = mf * Wc[m];
    float p1 = mf * Wc[M_ + m];

    red[m] = p0;
    __syncthreads();
    for (int s = 256; s > 0; s >>= 1) {
        if (m < s) red[m] += red[m + s];
        __syncthreads();
    }
    const float o0 = red[0];
    __syncthreads();

    red[m] = p1;
    __syncthreads();
    for (int s = 256; s > 0; s >>= 1) {
        if (m < s) red[m] += red[m + s];
        __syncthreads();
    }
    if (m == 0) {
        out[(size_t)b * 2 + 0] = o0     + bc[0] * bias_rel;
        out[(size_t)b * 2 + 1] = red[0] + bc[1] * bias_rel;
    }
}

// ---------------------------------------------------------------------------
// Launch: d_out = (out[256,2], A_sftmx[256,500], A_pre[256,1,500])
// ---------------------------------------------------------------------------
extern "C" void kernel_launch(void* const* d_in, const int* in_sizes, int n_in,
                              void* d_out, int out_size)
{
    const float* H  = (const float*)d_in[0];
    const float* Wv = (const float*)d_in[1];
    const float* bv = (const float*)d_in[2];
    const float* Wu = (const float*)d_in[3];
    const float* bu = (const float*)d_in[4];
    const float* Ww = (const float*)d_in[5];
    const float* bw = (const float*)d_in[6];
    const float* Wc = (const float*)d_in[7];
    const float* bc = (const float*)d_in[8];

    float* out   = (float*)d_out;               // [256,2]
    float* A_sm  = out + (size_t)B_ * 2;        // [256,500]
    float* A_pre = A_sm + (size_t)B_ * T_;      // [256,1,500]

    cudaFuncSetAttribute(mil_phase1_mma,
                         cudaFuncAttributeMaxDynamicSharedMemorySize, SMEM_P1);

    wsplit_kernel<<<(NN * M_) / 256, 256>>>(Wv, Wu);
    mil_phase1_mma<<<NROWS / MT, NTH, SMEM_P1>>>(H, bv, bu, Ww, bw, A_pre);
    mil_softmax<<<B_, 256>>>(A_pre, A_sm);
    mil_phase3<<<B_, 512>>>(H, A_sm, Wc, bc, out);
}

// round 7
// speedup vs baseline: 2.3739x; 1.1204x over previous
#include <cuda_runtime.h>
#include <cuda_bf16.h>
#include <stdint.h>
#include <math.h>

#define B_   256
#define T_   500
#define M_   512
#define L_   128
#define NROWS (B_ * T_)    // 128000

// ---- phase-1 tiling ----
#define MT   128            // rows / CTA
#define NN   256            // cols (V:0..127, U:128..255)
#define KC   64             // fp32 k per stage -> 128B bf16 rows (SW128)
#define NST  (M_ / KC)      // 8 stages
#define NTH  512

// smem: two stages of {Ahi 16K, Alo 16K, Bhi 32K, Blo 32K} = 96KB each, + Wc 4K
#define BUF     98304
#define SMEM_P1 (2 * BUF + 4096)   // 200704

// W pre-split (bf16 hi/lo), [n][k] row-major, 16B aligned
__device__ __align__(16) unsigned short g_Whi[NN * M_];
__device__ __align__(16) unsigned short g_Wlo[NN * M_];
// fused per-row projection dots: G[b*T+t][k] = H[b,t,:]. Wc[k,:]
__device__ float g_G[NROWS * 2];

// ===================== helpers =====================
__device__ __forceinline__ uint32_t smem_u32(const void* p) {
    uint32_t a;
    asm("{ .reg .u64 t; cvta.to.shared.u64 t, %1; cvt.u32.u64 %0, t; }"
        : "=r"(a) : "l"(p));
    return a;
}
__device__ __forceinline__ uint32_t swz(uint32_t o) { return o ^ ((o >> 3) & 0x70); }

__device__ __forceinline__ void ldsm4(uint32_t a, uint32_t& r0, uint32_t& r1,
                                      uint32_t& r2, uint32_t& r3) {
    asm volatile("ldmatrix.sync.aligned.m8n8.x4.shared.b16 {%0,%1,%2,%3}, [%4];"
                 : "=r"(r0), "=r"(r1), "=r"(r2), "=r"(r3) : "r"(a));
}
__device__ __forceinline__ void mma16816(float* c, uint32_t a0, uint32_t a1,
                                         uint32_t a2, uint32_t a3,
                                         uint32_t b0, uint32_t b1) {
    asm volatile(
        "mma.sync.aligned.m16n8k16.row.col.f32.bf16.bf16.f32 "
        "{%0,%1,%2,%3}, {%4,%5,%6,%7}, {%8,%9}, {%0,%1,%2,%3};"
        : "+f"(c[0]), "+f"(c[1]), "+f"(c[2]), "+f"(c[3])
        : "r"(a0), "r"(a1), "r"(a2), "r"(a3), "r"(b0), "r"(b1));
}
#define CP16(dst, src) \
    asm volatile("cp.async.cg.shared.global [%0], [%1], 16;" :: "r"(dst), "l"(src))
#define CP_COMMIT() asm volatile("cp.async.commit_group;" ::: "memory")
#define CP_WAIT0()  asm volatile("cp.async.wait_group 0;" ::: "memory")
#define STS128(a, x, y, z, w) \
    asm volatile("st.shared.v4.b32 [%0], {%1,%2,%3,%4};" \
                 :: "r"(a), "r"(x), "r"(y), "r"(z), "r"(w))

__device__ __forceinline__ uint32_t pack2(__nv_bfloat16 a, __nv_bfloat16 b) {
    return ((uint32_t)__bfloat16_as_ushort(b) << 16) | (uint32_t)__bfloat16_as_ushort(a);
}
__device__ __forceinline__ void split_pair(float x, float y, uint32_t& hw, uint32_t& lw) {
    __nv_bfloat16 hx = __float2bfloat16(x);
    __nv_bfloat16 hy = __float2bfloat16(y);
    __nv_bfloat16 lx = __float2bfloat16(x - __bfloat162float(hx));
    __nv_bfloat16 ly = __float2bfloat16(y - __bfloat162float(hy));
    hw = pack2(hx, hy);
    lw = pack2(lx, ly);
}

// ---------------------------------------------------------------------------
// Pre-split W = [Wv;Wu] into bf16 hi/lo (once per launch; 512KB)
// ---------------------------------------------------------------------------
__global__ void wsplit_kernel(const float* __restrict__ Wv, const float* __restrict__ Wu)
{
    int idx = blockIdx.x * 256 + threadIdx.x;          // 0 .. 131071
    int n = idx >> 9, k = idx & 511;
    float x = (n < L_) ? Wv[n * M_ + k] : Wu[(n - L_) * M_ + k];
    __nv_bfloat16 h = __float2bfloat16(x);
    __nv_bfloat16 l = __float2bfloat16(x - __bfloat162float(h));
    g_Whi[idx] = __bfloat16_as_ushort(h);
    g_Wlo[idx] = __bfloat16_as_ushort(l);
}

// ---------------------------------------------------------------------------
// Phase 1: mma.sync bf16-split GEMM + fused activation epilogue -> A_pre
//          + fused per-row Wc projection dots -> g_G
// ---------------------------------------------------------------------------
__device__ __forceinline__ void load_B_async(uint32_t bufb, int kt, int tid)
{
    const int row = tid >> 1, half = tid & 1;
    const unsigned short* sh = g_Whi + row * M_ + kt * KC + half * 32;
    const unsigned short* sl = g_Wlo + row * M_ + kt * KC + half * 32;
    const uint32_t dh = bufb + 32768, dl = bufb + 65536;
#pragma unroll
    for (int j = 0; j < 4; ++j) {
        uint32_t off = swz((uint32_t)(row * 128 + (half * 4 + j) * 16));
        CP16(dh + off, sh + j * 8);
        CP16(dl + off, sl + j * 8);
    }
}

__device__ __forceinline__ void sts_A(uint32_t bufb, const float4* f, int tid)
{
    const int row = tid >> 2, q = tid & 3;
    uint32_t h0, h1, h2, h3, l0, l1, l2, l3;
    split_pair(f[0].x, f[0].y, h0, l0);
    split_pair(f[0].z, f[0].w, h1, l1);
    split_pair(f[1].x, f[1].y, h2, l2);
    split_pair(f[1].z, f[1].w, h3, l3);
    uint32_t o0 = swz((uint32_t)(row * 128 + q * 32));
    STS128(bufb + o0, h0, h1, h2, h3);
    STS128(bufb + 16384 + o0, l0, l1, l2, l3);
    split_pair(f[2].x, f[2].y, h0, l0);
    split_pair(f[2].z, f[2].w, h1, l1);
    split_pair(f[3].x, f[3].y, h2, l2);
    split_pair(f[3].z, f[3].w, h3, l3);
    uint32_t o1 = swz((uint32_t)(row * 128 + q * 32 + 16));
    STS128(bufb + o1, h0, h1, h2, h3);
    STS128(bufb + 16384 + o1, l0, l1, l2, l3);
}

// accumulate G partial dots from an fp32 A fragment (16 k values)
__device__ __forceinline__ void acc_G(const float* WcS, const float4* f, int kbase,
                                      float& pd0, float& pd1)
{
#pragma unroll
    for (int i = 0; i < 4; ++i) {
        float4 w0 = *reinterpret_cast<const float4*>(WcS + kbase + i * 4);
        float4 w1 = *reinterpret_cast<const float4*>(WcS + 512 + kbase + i * 4);
        pd0 += f[i].x * w0.x + f[i].y * w0.y + f[i].z * w0.z + f[i].w * w0.w;
        pd1 += f[i].x * w1.x + f[i].y * w1.y + f[i].z * w1.z + f[i].w * w1.w;
    }
}

#define UPAD 133   // floats per Uact row (conflict-free)

__global__ __launch_bounds__(NTH, 1)
void mil_phase1_mma(const float* __restrict__ H,
                    const float* __restrict__ bv, const float* __restrict__ bu,
                    const float* __restrict__ Ww, const float* __restrict__ bw,
                    const float* __restrict__ Wc,
                    float* __restrict__ A_pre)
{
    extern __shared__ __align__(1024) char smem[];
    const uint32_t sb = smem_u32(smem);
    const int tid  = threadIdx.x;
    const int lane = tid & 31;
    const int warp = tid >> 5;
    const int rw   = warp >> 2;      // 0..3 row group (32 rows)
    const int cw   = warp & 3;       // 0..3 col group (64 cols)
    const int row0 = blockIdx.x * MT;

    float* WcS = reinterpret_cast<float*>(smem + 2 * BUF);   // [2][512]
    WcS[tid]       = Wc[tid];
    WcS[tid + 512] = Wc[tid + 512];

    float acc[2][4][2][4];
#pragma unroll
    for (int a = 0; a < 2; ++a)
#pragma unroll
        for (int b = 0; b < 4; ++b)
#pragma unroll
            for (int c = 0; c < 2; ++c)
#pragma unroll
                for (int d = 0; d < 4; ++d) acc[a][b][c][d] = 0.f;

    const float* gA = H + (size_t)(row0 + (tid >> 2)) * M_ + (tid & 3) * 16;
    const int kb0 = (tid & 3) * 16;       // k base of this thread's fragment
    float pd0 = 0.f, pd1 = 0.f;           // G partial dots

    // ldmatrix per-lane address components
    const int lrow = lane & 15;
    const int lko  = (lane >> 4) * 16;
    const int arow0 = (rw * 32 + lrow) * 128;          // mt=0
    const int arow1 = (rw * 32 + 16 + lrow) * 128;     // mt=1

    // ---- prologue: stage 0 ----
    load_B_async(sb, 0, tid);
    CP_COMMIT();
    float4 f0[4];
#pragma unroll
    for (int i = 0; i < 4; ++i)
        f0[i] = *reinterpret_cast<const float4*>(gA + i * 4);
    sts_A(sb, f0, tid);
    CP_WAIT0();
    __syncthreads();            // also publishes WcS
    acc_G(WcS, f0, kb0, pd0, pd1);

    // ---- main loop ----
    for (int kt = 0; kt < NST; ++kt) {
        const uint32_t bufc = sb + (uint32_t)(kt & 1) * BUF;
        const uint32_t bufn = sb + (uint32_t)((kt + 1) & 1) * BUF;

        float4 fA[4];
        if (kt < NST - 1) {
            const float* s = gA + (kt + 1) * KC;
#pragma unroll
            for (int i = 0; i < 4; ++i)
                fA[i] = *reinterpret_cast<const float4*>(s + i * 4);
            load_B_async(bufn, kt + 1, tid);
            CP_COMMIT();
        }

        // compute stage kt: 4 k16-steps, 3 split products
#pragma unroll
        for (int ks = 0; ks < 4; ++ks) {
            const uint32_t kb = (uint32_t)(ks * 32 + lko);
            uint32_t ah[2][4], al[2][4];
            ldsm4(bufc + swz(arow0 + kb), ah[0][0], ah[0][1], ah[0][2], ah[0][3]);
            ldsm4(bufc + swz(arow1 + kb), ah[1][0], ah[1][1], ah[1][2], ah[1][3]);
            ldsm4(bufc + 16384 + swz(arow0 + kb), al[0][0], al[0][1], al[0][2], al[0][3]);
            ldsm4(bufc + 16384 + swz(arow1 + kb), al[1][0], al[1][1], al[1][2], al[1][3]);
#pragma unroll
            for (int ng = 0; ng < 4; ++ng) {
                const uint32_t bro = (uint32_t)((cw * 64 + ng * 16 + lrow) * 128) + kb;
                uint32_t bh0, bh1, bh2, bh3, bl0, bl1, bl2, bl3;
                ldsm4(bufc + 32768 + swz(bro), bh0, bh1, bh2, bh3);
                ldsm4(bufc + 65536 + swz(bro), bl0, bl1, bl2, bl3);
#pragma unroll
                for (int mt = 0; mt < 2; ++mt) {
                    mma16816(acc[mt][ng][0], ah[mt][0], ah[mt][1], ah[mt][2], ah[mt][3], bh0, bh2);
                    mma16816(acc[mt][ng][1], ah[mt][0], ah[mt][1], ah[mt][2], ah[mt][3], bh1, bh3);
                    mma16816(acc[mt][ng][0], ah[mt][0], ah[mt][1], ah[mt][2], ah[mt][3], bl0, bl2);
                    mma16816(acc[mt][ng][1], ah[mt][0], ah[mt][1], ah[mt][2], ah[mt][3], bl1, bl3);
                    mma16816(acc[mt][ng][0], al[mt][0], al[mt][1], al[mt][2], al[mt][3], bh0, bh2);
                    mma16816(acc[mt][ng][1], al[mt][0], al[mt][1], al[mt][2], al[mt][3], bh1, bh3);
                }
            }
        }

        if (kt < NST - 1) {
            acc_G(WcS, fA, kb0 + (kt + 1) * KC, pd0, pd1);
            sts_A(bufn, fA, tid);
            CP_WAIT0();
        }
        __syncthreads();
    }

    // ---- G write: reduce pd over the 4 threads sharing a row ----
    pd0 += __shfl_xor_sync(0xffffffffu, pd0, 1);
    pd0 += __shfl_xor_sync(0xffffffffu, pd0, 2);
    pd1 += __shfl_xor_sync(0xffffffffu, pd1, 1);
    pd1 += __shfl_xor_sync(0xffffffffu, pd1, 2);
    if ((tid & 3) == 0) {
        const size_t gr = (size_t)(row0 + (tid >> 2)) * 2;
        g_G[gr]     = pd0;
        g_G[gr + 1] = pd1;
    }

    // ---- epilogue ----
    float* Uact = reinterpret_cast<float*>(smem);              // [128][UPAD]
    float* part = reinterpret_cast<float*>(smem) + 128 * UPAD; // [2][128]

    if (cw >= 2) {   // U half: sigma(U + bu) -> Uact
#pragma unroll
        for (int mt = 0; mt < 2; ++mt)
#pragma unroll
            for (int ng = 0; ng < 4; ++ng)
#pragma unroll
                for (int h = 0; h < 2; ++h)
#pragma unroll
                    for (int e = 0; e < 4; ++e) {
                        int r  = rw * 32 + mt * 16 + (lane >> 2) + (e >= 2 ? 8 : 0);
                        int uc = (cw - 2) * 64 + ng * 16 + h * 8 + (lane & 3) * 2 + (e & 1);
                        float x = acc[mt][ng][h][e] + __ldg(&bu[uc]);
                        Uact[r * UPAD + uc] = 1.f / (1.f + expf(-x));
                    }
    }
    __syncthreads();

    if (cw < 2) {    // V half: tanh(V + bv)*Ww * Uact, row-reduce
        float srow[2][2] = {{0.f, 0.f}, {0.f, 0.f}};   // [mt][rhalf]
#pragma unroll
        for (int mt = 0; mt < 2; ++mt)
#pragma unroll
            for (int ng = 0; ng < 4; ++ng)
#pragma unroll
                for (int h = 0; h < 2; ++h)
#pragma unroll
                    for (int e = 0; e < 4; ++e) {
                        int rh = (e >= 2) ? 1 : 0;
                        int r  = rw * 32 + mt * 16 + (lane >> 2) + rh * 8;
                        int c  = cw * 64 + ng * 16 + h * 8 + (lane & 3) * 2 + (e & 1);
                        float x = acc[mt][ng][h][e] + __ldg(&bv[c]);
                        float v = tanhf(x) * __ldg(&Ww[c]);
                        srow[mt][rh] += v * Uact[r * UPAD + c];
                    }
#pragma unroll
        for (int mt = 0; mt < 2; ++mt)
#pragma unroll
            for (int rh = 0; rh < 2; ++rh) {
                srow[mt][rh] += __shfl_xor_sync(0xffffffffu, srow[mt][rh], 1);
                srow[mt][rh] += __shfl_xor_sync(0xffffffffu, srow[mt][rh], 2);
            }
        if ((lane & 3) == 0) {
#pragma unroll
            for (int mt = 0; mt < 2; ++mt)
#pragma unroll
                for (int rh = 0; rh < 2; ++rh) {
                    int r = rw * 32 + mt * 16 + (lane >> 2) + rh * 8;
                    part[cw * 128 + r] = srow[mt][rh];
                }
        }
    }
    __syncthreads();

    if (tid < MT)
        A_pre[(size_t)(row0 + tid)] = part[tid] + part[128 + tid] + bw[0];
}

// ---------------------------------------------------------------------------
// Phase 2+3 merged: per-bag softmax -> A_sftmx, then
// out[b,k] = sum_t a[t]*G[b,t,k] + bc[k]*bias_rel
// ---------------------------------------------------------------------------
__global__ __launch_bounds__(256)
void mil_finish(const float* __restrict__ A_pre,
                const float* __restrict__ bc,
                float* __restrict__ Asm, float* __restrict__ out)
{
    __shared__ float sh0[256];
    __shared__ float sh1[256];
    __shared__ float sh2[256];
    const int b   = blockIdx.x;
    const int tid = threadIdx.x;
    const float* src = A_pre + (size_t)b * T_;

    const int t0 = tid, t1 = tid + 256;
    float v0 = src[t0];
    float v1 = (t1 < T_) ? src[t1] : -INFINITY;

    sh0[tid] = fmaxf(v0, v1);
    __syncthreads();
    for (int s = 128; s > 0; s >>= 1) {
        if (tid < s) sh0[tid] = fmaxf(sh0[tid], sh0[tid + s]);
        __syncthreads();
    }
    const float mx = sh0[0];
    __syncthreads();

    float e0 = expf(v0 - mx);
    float e1 = (t1 < T_) ? expf(v1 - mx) : 0.f;
    sh0[tid] = e0 + e1;
    __syncthreads();
    for (int s = 128; s > 0; s >>= 1) {
        if (tid < s) sh0[tid] += sh0[tid + s];
        __syncthreads();
    }
    const float inv = 1.f / sh0[0];
    __syncthreads();

    const float a0 = e0 * inv;
    const float a1 = e1 * inv;
    Asm[(size_t)b * T_ + t0] = a0;
    if (t1 < T_) Asm[(size_t)b * T_ + t1] = a1;

    const float* Gb = g_G + (size_t)b * T_ * 2;
    float c0 = a0 * Gb[t0 * 2]     + ((t1 < T_) ? a1 * Gb[t1 * 2]     : 0.f);
    float c1 = a0 * Gb[t0 * 2 + 1] + ((t1 < T_) ? a1 * Gb[t1 * 2 + 1] : 0.f);

    sh0[tid] = a0 + a1;   // bias_rel partial
    sh1[tid] = c0;
    sh2[tid] = c1;
    __syncthreads();
    for (int s = 128; s > 0; s >>= 1) {
        if (tid < s) {
            sh0[tid] += sh0[tid + s];
            sh1[tid] += sh1[tid + s];
            sh2[tid] += sh2[tid + s];
        }
        __syncthreads();
    }
    if (tid == 0) {
        const float bias_rel = sh0[0];
        out[(size_t)b * 2 + 0] = sh1[0] + bc[0] * bias_rel;
        out[(size_t)b * 2 + 1] = sh2[0] + bc[1] * bias_rel;
    }
}

// ---------------------------------------------------------------------------
// Launch: d_out = (out[256,2], A_sftmx[256,500], A_pre[256,1,500])
// ---------------------------------------------------------------------------
extern "C" void kernel_launch(void* const* d_in, const int* in_sizes, int n_in,
                              void* d_out, int out_size)
{
    const float* H  = (const float*)d_in[0];
    const float* Wv = (const float*)d_in[1];
    const float* bv = (const float*)d_in[2];
    const float* Wu = (const float*)d_in[3];
    const float* bu = (const float*)d_in[4];
    const float* Ww = (const float*)d_in[5];
    const float* bw = (const float*)d_in[6];
    const float* Wc = (const float*)d_in[7];
    const float* bc = (const float*)d_in[8];

    float* out   = (float*)d_out;               // [256,2]
    float* A_sm  = out + (size_t)B_ * 2;        // [256,500]
    float* A_pre = A_sm + (size_t)B_ * T_;      // [256,1,500]

    // one-time, non-stream host config (no-op during graph capture replays)
    static bool configured = false;
    if (!configured) {
        cudaFuncSetAttribute(mil_phase1_mma,
                             cudaFuncAttributeMaxDynamicSharedMemorySize, SMEM_P1);
        configured = true;
    }

    wsplit_kernel<<<(NN * M_) / 256, 256>>>(Wv, Wu);
    mil_phase1_mma<<<NROWS / MT, NTH, SMEM_P1>>>(H, bv, bu, Ww, bw, Wc, A_pre);
    mil_finish<<<B_, 256>>>(A_pre, bc, A_sm, out);
}

// round 9
// speedup vs baseline: 3.0237x; 1.2737x over previous
#include <cuda_runtime.h>
#include <cuda_fp16.h>
#include <stdint.h>
#include <math.h>

#define B_   256
#define T_   500
#define M_   512
#define L_   128
#define NROWS (B_ * T_)    // 128000

// ---- phase-1 tiling ----
#define MT   128            // rows / CTA
#define NN   256            // cols (V:0..127, U:128..255)
#define KC   64             // fp32 k per stage -> 128B fp16 rows (SW128)
#define NST  (M_ / KC)      // 8 stages
#define NTH  512

// smem stage: {Ahi 16K, Bhi 32K, Blo 32K} = 80KB; two stages + Wc 4K
#define BUF     81920
#define SMEM_P1 (2 * BUF + 4096)   // 167936

// W pre-split (fp16 hi/lo), [n][k] row-major, 16B aligned
__device__ __align__(16) unsigned short g_Whi[NN * M_];
__device__ __align__(16) unsigned short g_Wlo[NN * M_];
// fused per-row projection dots: G[b*T+t][k] = H[b,t,:]. Wc[k,:]
__device__ float g_G[NROWS * 2];

// ===================== helpers =====================
__device__ __forceinline__ uint32_t smem_u32(const void* p) {
    uint32_t a;
    asm("{ .reg .u64 t; cvta.to.shared.u64 t, %1; cvt.u32.u64 %0, t; }"
        : "=r"(a) : "l"(p));
    return a;
}
__device__ __forceinline__ uint32_t swz(uint32_t o) { return o ^ ((o >> 3) & 0x70); }

__device__ __forceinline__ void ldsm4(uint32_t a, uint32_t& r0, uint32_t& r1,
                                      uint32_t& r2, uint32_t& r3) {
    asm volatile("ldmatrix.sync.aligned.m8n8.x4.shared.b16 {%0,%1,%2,%3}, [%4];"
                 : "=r"(r0), "=r"(r1), "=r"(r2), "=r"(r3) : "r"(a));
}
__device__ __forceinline__ void mma16816(float* c, uint32_t a0, uint32_t a1,
                                         uint32_t a2, uint32_t a3,
                                         uint32_t b0, uint32_t b1) {
    asm volatile(
        "mma.sync.aligned.m16n8k16.row.col.f32.f16.f16.f32 "
        "{%0,%1,%2,%3}, {%4,%5,%6,%7}, {%8,%9}, {%0,%1,%2,%3};"
        : "+f"(c[0]), "+f"(c[1]), "+f"(c[2]), "+f"(c[3])
        : "r"(a0), "r"(a1), "r"(a2), "r"(a3), "r"(b0), "r"(b1));
}
#define CP16(dst, src) \
    asm volatile("cp.async.cg.shared.global [%0], [%1], 16;" :: "r"(dst), "l"(src))
#define CP_COMMIT() asm volatile("cp.async.commit_group;" ::: "memory")
#define CP_WAIT0()  asm volatile("cp.async.wait_group 0;" ::: "memory")
#define STS128(a, x, y, z, w) \
    asm volatile("st.shared.v4.b32 [%0], {%1,%2,%3,%4};" \
                 :: "r"(a), "r"(x), "r"(y), "r"(z), "r"(w))

__device__ __forceinline__ uint32_t h2_u32(float a, float b) {
    __half2 h = __floats2half2_rn(a, b);
    return *reinterpret_cast<uint32_t*>(&h);
}

// ---------------------------------------------------------------------------
// Pre-split W = [Wv;Wu] into fp16 hi/lo (once per launch; 512KB)
// ---------------------------------------------------------------------------
__global__ void wsplit_kernel(const float* __restrict__ Wv, const float* __restrict__ Wu)
{
    int idx = blockIdx.x * 256 + threadIdx.x;          // 0 .. 131071
    int n = idx >> 9, k = idx & 511;
    float x = (n < L_) ? Wv[n * M_ + k] : Wu[(n - L_) * M_ + k];
    __half h = __float2half_rn(x);
    __half l = __float2half_rn(x - __half2float(h));
    g_Whi[idx] = *reinterpret_cast<unsigned short*>(&h);
    g_Wlo[idx] = *reinterpret_cast<unsigned short*>(&l);
}

// ---------------------------------------------------------------------------
// Phase 1: mma.sync fp16 2-product GEMM + fused activation epilogue -> A_pre
//          + fused per-row Wc projection dots -> g_G
// C = hiA.hiB + hiA.loB  (loA dropped; rel err ~2^-11 on the GEMM element)
// ---------------------------------------------------------------------------
__device__ __forceinline__ void load_B_async(uint32_t bufb, int kt, int tid)
{
    const int row = tid >> 1, half = tid & 1;
    const unsigned short* sh = g_Whi + row * M_ + kt * KC + half * 32;
    const unsigned short* sl = g_Wlo + row * M_ + kt * KC + half * 32;
    const uint32_t dh = bufb + 16384, dl = bufb + 49152;
#pragma unroll
    for (int j = 0; j < 4; ++j) {
        uint32_t off = swz((uint32_t)(row * 128 + (half * 4 + j) * 16));
        CP16(dh + off, sh + j * 8);
        CP16(dl + off, sl + j * 8);
    }
}

// store A tile as fp16 hi only (16 floats/thread)
__device__ __forceinline__ void sts_A(uint32_t bufb, const float4* f, int tid)
{
    const int row = tid >> 2, q = tid & 3;
    uint32_t w0 = h2_u32(f[0].x, f[0].y);
    uint32_t w1 = h2_u32(f[0].z, f[0].w);
    uint32_t w2 = h2_u32(f[1].x, f[1].y);
    uint32_t w3 = h2_u32(f[1].z, f[1].w);
    STS128(bufb + swz((uint32_t)(row * 128 + q * 32)), w0, w1, w2, w3);
    w0 = h2_u32(f[2].x, f[2].y);
    w1 = h2_u32(f[2].z, f[2].w);
    w2 = h2_u32(f[3].x, f[3].y);
    w3 = h2_u32(f[3].z, f[3].w);
    STS128(bufb + swz((uint32_t)(row * 128 + q * 32 + 16)), w0, w1, w2, w3);
}

// accumulate G partial dots from an fp32 A fragment (16 k values)
__device__ __forceinline__ void acc_G(const float* WcS, const float4* f, int kbase,
                                      float& pd0, float& pd1)
{
#pragma unroll
    for (int i = 0; i < 4; ++i) {
        float4 w0 = *reinterpret_cast<const float4*>(WcS + kbase + i * 4);
        float4 w1 = *reinterpret_cast<const float4*>(WcS + 512 + kbase + i * 4);
        pd0 += f[i].x * w0.x + f[i].y * w0.y + f[i].z * w0.z + f[i].w * w0.w;
        pd1 += f[i].x * w1.x + f[i].y * w1.y + f[i].z * w1.z + f[i].w * w1.w;
    }
}

#define UPAD 133   // floats per Uact row (conflict-free)

__global__ __launch_bounds__(NTH, 1)
void mil_phase1_mma(const float* __restrict__ H,
                    const float* __restrict__ bv, const float* __restrict__ bu,
                    const float* __restrict__ Ww, const float* __restrict__ bw,
                    const float* __restrict__ Wc,
                    float* __restrict__ A_pre)
{
    extern __shared__ __align__(1024) char smem[];
    const uint32_t sb = smem_u32(smem);
    const int tid  = threadIdx.x;
    const int lane = tid & 31;
    const int warp = tid >> 5;
    const int rw   = warp >> 2;      // 0..3 row group (32 rows)
    const int cw   = warp & 3;       // 0..3 col group (64 cols)
    const int row0 = blockIdx.x * MT;

    float* WcS = reinterpret_cast<float*>(smem + 2 * BUF);   // [2][512]
    WcS[tid]       = Wc[tid];
    WcS[tid + 512] = Wc[tid + 512];

    float acc[2][4][2][4];
#pragma unroll
    for (int a = 0; a < 2; ++a)
#pragma unroll
        for (int b = 0; b < 4; ++b)
#pragma unroll
            for (int c = 0; c < 2; ++c)
#pragma unroll
                for (int d = 0; d < 4; ++d) acc[a][b][c][d] = 0.f;

    const float* gA = H + (size_t)(row0 + (tid >> 2)) * M_ + (tid & 3) * 16;
    const int kb0 = (tid & 3) * 16;       // k base of this thread's fragment
    float pd0 = 0.f, pd1 = 0.f;           // G partial dots

    // ldmatrix per-lane address components
    const int lrow = lane & 15;
    const int lko  = (lane >> 4) * 16;
    const int arow0 = (rw * 32 + lrow) * 128;          // mt=0
    const int arow1 = (rw * 32 + 16 + lrow) * 128;     // mt=1

    // ---- prologue: stage 0 ----
    load_B_async(sb, 0, tid);
    CP_COMMIT();
    float4 f0[4];
#pragma unroll
    for (int i = 0; i < 4; ++i)
        f0[i] = *reinterpret_cast<const float4*>(gA + i * 4);
    sts_A(sb, f0, tid);
    CP_WAIT0();
    __syncthreads();            // also publishes WcS
    acc_G(WcS, f0, kb0, pd0, pd1);

    // ---- main loop ----
    for (int kt = 0; kt < NST; ++kt) {
        const uint32_t bufc = sb + (uint32_t)(kt & 1) * BUF;
        const uint32_t bufn = sb + (uint32_t)((kt + 1) & 1) * BUF;

        float4 fA[4];
        if (kt < NST - 1) {
            const float* s = gA + (kt + 1) * KC;
#pragma unroll
            for (int i = 0; i < 4; ++i)
                fA[i] = *reinterpret_cast<const float4*>(s + i * 4);
            load_B_async(bufn, kt + 1, tid);
            CP_COMMIT();
        }

        // compute stage kt: 4 k16-steps, 2 products (hiA.hiB + hiA.loB)
#pragma unroll
        for (int ks = 0; ks < 4; ++ks) {
            const uint32_t kb = (uint32_t)(ks * 32 + lko);
            uint32_t ah[2][4];
            ldsm4(bufc + swz(arow0 + kb), ah[0][0], ah[0][1], ah[0][2], ah[0][3]);
            ldsm4(bufc + swz(arow1 + kb), ah[1][0], ah[1][1], ah[1][2], ah[1][3]);
#pragma unroll
            for (int ng = 0; ng < 4; ++ng) {
                const uint32_t bro = (uint32_t)((cw * 64 + ng * 16 + lrow) * 128) + kb;
                uint32_t bh0, bh1, bh2, bh3, bl0, bl1, bl2, bl3;
                ldsm4(bufc + 16384 + swz(bro), bh0, bh1, bh2, bh3);
                ldsm4(bufc + 49152 + swz(bro), bl0, bl1, bl2, bl3);
#pragma unroll
                for (int mt = 0; mt < 2; ++mt) {
                    mma16816(acc[mt][ng][0], ah[mt][0], ah[mt][1], ah[mt][2], ah[mt][3], bh0, bh2);
                    mma16816(acc[mt][ng][1], ah[mt][0], ah[mt][1], ah[mt][2], ah[mt][3], bh1, bh3);
                    mma16816(acc[mt][ng][0], ah[mt][0], ah[mt][1], ah[mt][2], ah[mt][3], bl0, bl2);
                    mma16816(acc[mt][ng][1], ah[mt][0], ah[mt][1], ah[mt][2], ah[mt][3], bl1, bl3);
                }
            }
        }

        if (kt < NST - 1) {
            acc_G(WcS, fA, kb0 + (kt + 1) * KC, pd0, pd1);
            sts_A(bufn, fA, tid);
            CP_WAIT0();
        }
        __syncthreads();
    }

    // ---- G write: reduce pd over the 4 threads sharing a row ----
    pd0 += __shfl_xor_sync(0xffffffffu, pd0, 1);
    pd0 += __shfl_xor_sync(0xffffffffu, pd0, 2);
    pd1 += __shfl_xor_sync(0xffffffffu, pd1, 1);
    pd1 += __shfl_xor_sync(0xffffffffu, pd1, 2);
    if ((tid & 3) == 0) {
        const size_t gr = (size_t)(row0 + (tid >> 2)) * 2;
        g_G[gr]     = pd0;
        g_G[gr + 1] = pd1;
    }

    // ---- epilogue ----
    float* Uact = reinterpret_cast<float*>(smem);              // [128][UPAD]
    float* part = reinterpret_cast<float*>(smem) + 128 * UPAD; // [2][128]

    if (cw >= 2) {   // U half: sigma(U + bu) -> Uact
#pragma unroll
        for (int mt = 0; mt < 2; ++mt)
#pragma unroll
            for (int ng = 0; ng < 4; ++ng)
#pragma unroll
                for (int h = 0; h < 2; ++h)
#pragma unroll
                    for (int e = 0; e < 4; ++e) {
                        int r  = rw * 32 + mt * 16 + (lane >> 2) + (e >= 2 ? 8 : 0);
                        int uc = (cw - 2) * 64 + ng * 16 + h * 8 + (lane & 3) * 2 + (e & 1);
                        float x = acc[mt][ng][h][e] + __ldg(&bu[uc]);
                        Uact[r * UPAD + uc] = 1.f / (1.f + expf(-x));
                    }
    }
    __syncthreads();

    if (cw < 2) {    // V half: tanh(V + bv)*Ww * Uact, row-reduce
        float srow[2][2] = {{0.f, 0.f}, {0.f, 0.f}};   // [mt][rhalf]
#pragma unroll
        for (int mt = 0; mt < 2; ++mt)
#pragma unroll
            for (int ng = 0; ng < 4; ++ng)
#pragma unroll
                for (int h = 0; h < 2; ++h)
#pragma unroll
                    for (int e = 0; e < 4; ++e) {
                        int rh = (e >= 2) ? 1 : 0;
                        int r  = rw * 32 + mt * 16 + (lane >> 2) + rh * 8;
                        int c  = cw * 64 + ng * 16 + h * 8 + (lane & 3) * 2 + (e & 1);
                        float x = acc[mt][ng][h][e] + __ldg(&bv[c]);
                        float v = tanhf(x) * __ldg(&Ww[c]);
                        srow[mt][rh] += v * Uact[r * UPAD + c];
                    }
#pragma unroll
        for (int mt = 0; mt < 2; ++mt)
#pragma unroll
            for (int rh = 0; rh < 2; ++rh) {
                srow[mt][rh] += __shfl_xor_sync(0xffffffffu, srow[mt][rh], 1);
                srow[mt][rh] += __shfl_xor_sync(0xffffffffu, srow[mt][rh], 2);
            }
        if ((lane & 3) == 0) {
#pragma unroll
            for (int mt = 0; mt < 2; ++mt)
#pragma unroll
                for (int rh = 0; rh < 2; ++rh) {
                    int r = rw * 32 + mt * 16 + (lane >> 2) + rh * 8;
                    part[cw * 128 + r] = srow[mt][rh];
                }
        }
    }
    __syncthreads();

    if (tid < MT)
        A_pre[(size_t)(row0 + tid)] = part[tid] + part[128 + tid] + bw[0];
}

// ---------------------------------------------------------------------------
// Phase 2+3 merged: per-bag softmax -> A_sftmx, then
// out[b,k] = sum_t a[t]*G[b,t,k] + bc[k]*bias_rel
// ---------------------------------------------------------------------------
__global__ __launch_bounds__(256)
void mil_finish(const float* __restrict__ A_pre,
                const float* __restrict__ bc,
                float* __restrict__ Asm, float* __restrict__ out)
{
    __shared__ float sh0[256];
    __shared__ float sh1[256];
    __shared__ float sh2[256];
    const int b   = blockIdx.x;
    const int tid = threadIdx.x;
    const float* src = A_pre + (size_t)b * T_;

    const int t0 = tid, t1 = tid + 256;
    float v0 = src[t0];
    float v1 = (t1 < T_) ? src[t1] : -INFINITY;

    sh0[tid] = fmaxf(v0, v1);
    __syncthreads();
    for (int s = 128; s > 0; s >>= 1) {
        if (tid < s) sh0[tid] = fmaxf(sh0[tid], sh0[tid + s]);
        __syncthreads();
    }
    const float mx = sh0[0];
    __syncthreads();

    float e0 = expf(v0 - mx);
    float e1 = (t1 < T_) ? expf(v1 - mx) : 0.f;
    sh0[tid] = e0 + e1;
    __syncthreads();
    for (int s = 128; s > 0; s >>= 1) {
        if (tid < s) sh0[tid] += sh0[tid + s];
        __syncthreads();
    }
    const float inv = 1.f / sh0[0];
    __syncthreads();

    const float a0 = e0 * inv;
    const float a1 = e1 * inv;
    Asm[(size_t)b * T_ + t0] = a0;
    if (t1 < T_) Asm[(size_t)b * T_ + t1] = a1;

    const float* Gb = g_G + (size_t)b * T_ * 2;
    float c0 = a0 * Gb[t0 * 2]     + ((t1 < T_) ? a1 * Gb[t1 * 2]     : 0.f);
    float c1 = a0 * Gb[t0 * 2 + 1] + ((t1 < T_) ? a1 * Gb[t1 * 2 + 1] : 0.f);

    sh0[tid] = a0 + a1;   // bias_rel partial
    sh1[tid] = c0;
    sh2[tid] = c1;
    __syncthreads();
    for (int s = 128; s > 0; s >>= 1) {
        if (tid < s) {
            sh0[tid] += sh0[tid + s];
            sh1[tid] += sh1[tid + s];
            sh2[tid] += sh2[tid + s];
        }
        __syncthreads();
    }
    if (tid == 0) {
        const float bias_rel = sh0[0];
        out[(size_t)b * 2 + 0] = sh1[0] + bc[0] * bias_rel;
        out[(size_t)b * 2 + 1] = sh2[0] + bc[1] * bias_rel;
    }
}

// ---------------------------------------------------------------------------
// Launch: d_out = (out[256,2], A_sftmx[256,500], A_pre[256,1,500])
// ---------------------------------------------------------------------------
extern "C" void kernel_launch(void* const* d_in, const int* in_sizes, int n_in,
                              void* d_out, int out_size)
{
    const float* H  = (const float*)d_in[0];
    const float* Wv = (const float*)d_in[1];
    const float* bv = (const float*)d_in[2];
    const float* Wu = (const float*)d_in[3];
    const float* bu = (const float*)d_in[4];
    const float* Ww = (const float*)d_in[5];
    const float* bw = (const float*)d_in[6];
    const float* Wc = (const float*)d_in[7];
    const float* bc = (const float*)d_in[8];

    float* out   = (float*)d_out;               // [256,2]
    float* A_sm  = out + (size_t)B_ * 2;        // [256,500]
    float* A_pre = A_sm + (size_t)B_ * T_;      // [256,1,500]

    // one-time, non-stream host config (no-op during graph capture replays)
    static bool configured = false;
    if (!configured) {
        cudaFuncSetAttribute(mil_phase1_mma,
                             cudaFuncAttributeMaxDynamicSharedMemorySize, SMEM_P1);
        configured = true;
    }

    wsplit_kernel<<<(NN * M_) / 256, 256>>>(Wv, Wu);
    mil_phase1_mma<<<NROWS / MT, NTH, SMEM_P1>>>(H, bv, bu, Ww, bw, Wc, A_pre);
    mil_finish<<<B_, 256>>>(A_pre, bc, A_sm, out);
}

// round 10
// speedup vs baseline: 4.1158x; 1.3611x over previous
#include <cuda_runtime.h>
#include <cuda_fp16.h>
#include <stdint.h>
#include <math.h>

#define B_   256
#define T_   500
#define M_   512
#define L_   128
#define NROWS (B_ * T_)    // 128000

// ---- phase-1 tiling ----
#define MT   128            // rows / CTA
#define NN   256            // cols (V:0..127, U:128..255)
#define KC   64             // fp32 k per stage -> 128B fp16 rows (SW128)
#define NST  (M_ / KC)      // 8 stages
#define NTH  512

// smem stage: {A 16K, B 32K} = 48KB; two stages + Wc 4K = 100KB -> 2 CTAs/SM
#define BUF     49152
#define SMEM_P1 (2 * BUF + 4096)   // 102400

// W (fp16), [n][k] row-major, 16B aligned
__device__ __align__(16) unsigned short g_Whi[NN * M_];
// fused per-row projection dots: G[b*T+t][k] = H[b,t,:]. Wc[k,:]
__device__ float g_G[NROWS * 2];

// ===================== helpers =====================
__device__ __forceinline__ uint32_t smem_u32(const void* p) {
    uint32_t a;
    asm("{ .reg .u64 t; cvta.to.shared.u64 t, %1; cvt.u32.u64 %0, t; }"
        : "=r"(a) : "l"(p));
    return a;
}
__device__ __forceinline__ uint32_t swz(uint32_t o) { return o ^ ((o >> 3) & 0x70); }

__device__ __forceinline__ void ldsm4(uint32_t a, uint32_t& r0, uint32_t& r1,
                                      uint32_t& r2, uint32_t& r3) {
    asm volatile("ldmatrix.sync.aligned.m8n8.x4.shared.b16 {%0,%1,%2,%3}, [%4];"
                 : "=r"(r0), "=r"(r1), "=r"(r2), "=r"(r3) : "r"(a));
}
__device__ __forceinline__ void mma16816(float* c, uint32_t a0, uint32_t a1,
                                         uint32_t a2, uint32_t a3,
                                         uint32_t b0, uint32_t b1) {
    asm volatile(
        "mma.sync.aligned.m16n8k16.row.col.f32.f16.f16.f32 "
        "{%0,%1,%2,%3}, {%4,%5,%6,%7}, {%8,%9}, {%0,%1,%2,%3};"
        : "+f"(c[0]), "+f"(c[1]), "+f"(c[2]), "+f"(c[3])
        : "r"(a0), "r"(a1), "r"(a2), "r"(a3), "r"(b0), "r"(b1));
}
#define CP16(dst, src) \
    asm volatile("cp.async.cg.shared.global [%0], [%1], 16;" :: "r"(dst), "l"(src))
#define CP_COMMIT() asm volatile("cp.async.commit_group;" ::: "memory")
#define CP_WAIT0()  asm volatile("cp.async.wait_group 0;" ::: "memory")
#define STS128(a, x, y, z, w) \
    asm volatile("st.shared.v4.b32 [%0], {%1,%2,%3,%4};" \
                 :: "r"(a), "r"(x), "r"(y), "r"(z), "r"(w))

__device__ __forceinline__ uint32_t h2_u32(float a, float b) {
    __half2 h = __floats2half2_rn(a, b);
    return *reinterpret_cast<uint32_t*>(&h);
}

// ---------------------------------------------------------------------------
// Convert W = [Wv;Wu] to fp16 (once per launch; 256KB)
// ---------------------------------------------------------------------------
__global__ void wsplit_kernel(const float* __restrict__ Wv, const float* __restrict__ Wu)
{
    int idx = blockIdx.x * 256 + threadIdx.x;          // 0 .. 131071
    int n = idx >> 9, k = idx & 511;
    float x = (n < L_) ? Wv[n * M_ + k] : Wu[(n - L_) * M_ + k];
    __half h = __float2half_rn(x);
    g_Whi[idx] = *reinterpret_cast<unsigned short*>(&h);
}

// ---------------------------------------------------------------------------
// Phase 1: plain fp16 mma.sync GEMM (fp32 acc) + fused activation -> A_pre
//          + fused per-row Wc projection dots -> g_G
// ---------------------------------------------------------------------------
__device__ __forceinline__ void load_B_async(uint32_t bufb, int kt, int tid)
{
    const int row = tid >> 1, half = tid & 1;
    const unsigned short* sh = g_Whi + row * M_ + kt * KC + half * 32;
    const uint32_t dh = bufb + 16384;
#pragma unroll
    for (int j = 0; j < 4; ++j) {
        uint32_t off = swz((uint32_t)(row * 128 + (half * 4 + j) * 16));
        CP16(dh + off, sh + j * 8);
    }
}

// store A tile as fp16 (16 floats/thread)
__device__ __forceinline__ void sts_A(uint32_t bufb, const float4* f, int tid)
{
    const int row = tid >> 2, q = tid & 3;
    uint32_t w0 = h2_u32(f[0].x, f[0].y);
    uint32_t w1 = h2_u32(f[0].z, f[0].w);
    uint32_t w2 = h2_u32(f[1].x, f[1].y);
    uint32_t w3 = h2_u32(f[1].z, f[1].w);
    STS128(bufb + swz((uint32_t)(row * 128 + q * 32)), w0, w1, w2, w3);
    w0 = h2_u32(f[2].x, f[2].y);
    w1 = h2_u32(f[2].z, f[2].w);
    w2 = h2_u32(f[3].x, f[3].y);
    w3 = h2_u32(f[3].z, f[3].w);
    STS128(bufb + swz((uint32_t)(row * 128 + q * 32 + 16)), w0, w1, w2, w3);
}

// accumulate G partial dots from an fp32 A fragment (16 k values)
__device__ __forceinline__ void acc_G(const float* WcS, const float4* f, int kbase,
                                      float& pd0, float& pd1)
{
#pragma unroll
    for (int i = 0; i < 4; ++i) {
        float4 w0 = *reinterpret_cast<const float4*>(WcS + kbase + i * 4);
        float4 w1 = *reinterpret_cast<const float4*>(WcS + 512 + kbase + i * 4);
        pd0 += f[i].x * w0.x + f[i].y * w0.y + f[i].z * w0.z + f[i].w * w0.w;
        pd1 += f[i].x * w1.x + f[i].y * w1.y + f[i].z * w1.z + f[i].w * w1.w;
    }
}

#define UPAD 133   // floats per Uact row (conflict-free)

__global__ __launch_bounds__(NTH, 1)
void mil_phase1_mma(const float* __restrict__ H,
                    const float* __restrict__ bv, const float* __restrict__ bu,
                    const float* __restrict__ Ww, const float* __restrict__ bw,
                    const float* __restrict__ Wc,
                    float* __restrict__ A_pre)
{
    extern __shared__ __align__(1024) char smem[];
    const uint32_t sb = smem_u32(smem);
    const int tid  = threadIdx.x;
    const int lane = tid & 31;
    const int warp = tid >> 5;
    const int rw   = warp >> 2;      // 0..3 row group (32 rows)
    const int cw   = warp & 3;       // 0..3 col group (64 cols)
    const int row0 = blockIdx.x * MT;

    float* WcS = reinterpret_cast<float*>(smem + 2 * BUF);   // [2][512]
    WcS[tid]       = Wc[tid];
    WcS[tid + 512] = Wc[tid + 512];

    float acc[2][4][2][4];
#pragma unroll
    for (int a = 0; a < 2; ++a)
#pragma unroll
        for (int b = 0; b < 4; ++b)
#pragma unroll
            for (int c = 0; c < 2; ++c)
#pragma unroll
                for (int d = 0; d < 4; ++d) acc[a][b][c][d] = 0.f;

    const float* gA = H + (size_t)(row0 + (tid >> 2)) * M_ + (tid & 3) * 16;
    const int kb0 = (tid & 3) * 16;       // k base of this thread's fragment
    float pd0 = 0.f, pd1 = 0.f;           // G partial dots

    // ldmatrix per-lane address components
    const int lrow = lane & 15;
    const int lko  = (lane >> 4) * 16;
    const int arow0 = (rw * 32 + lrow) * 128;          // mt=0
    const int arow1 = (rw * 32 + 16 + lrow) * 128;     // mt=1

    // ---- prologue: stage 0 ----
    load_B_async(sb, 0, tid);
    CP_COMMIT();
    float4 f0[4];
#pragma unroll
    for (int i = 0; i < 4; ++i)
        f0[i] = *reinterpret_cast<const float4*>(gA + i * 4);
    sts_A(sb, f0, tid);
    CP_WAIT0();
    __syncthreads();            // also publishes WcS
    acc_G(WcS, f0, kb0, pd0, pd1);

    // ---- main loop ----
    for (int kt = 0; kt < NST; ++kt) {
        const uint32_t bufc = sb + (uint32_t)(kt & 1) * BUF;
        const uint32_t bufn = sb + (uint32_t)((kt + 1) & 1) * BUF;

        float4 fA[4];
        if (kt < NST - 1) {
            const float* s = gA + (kt + 1) * KC;
#pragma unroll
            for (int i = 0; i < 4; ++i)
                fA[i] = *reinterpret_cast<const float4*>(s + i * 4);
            load_B_async(bufn, kt + 1, tid);
            CP_COMMIT();
        }

        // compute stage kt: 4 k16-steps, single fp16 product
#pragma unroll
        for (int ks = 0; ks < 4; ++ks) {
            const uint32_t kb = (uint32_t)(ks * 32 + lko);
            uint32_t ah[2][4];
            ldsm4(bufc + swz(arow0 + kb), ah[0][0], ah[0][1], ah[0][2], ah[0][3]);
            ldsm4(bufc + swz(arow1 + kb), ah[1][0], ah[1][1], ah[1][2], ah[1][3]);
#pragma unroll
            for (int ng = 0; ng < 4; ++ng) {
                const uint32_t bro = (uint32_t)((cw * 64 + ng * 16 + lrow) * 128) + kb;
                uint32_t bh0, bh1, bh2, bh3;
                ldsm4(bufc + 16384 + swz(bro), bh0, bh1, bh2, bh3);
#pragma unroll
                for (int mt = 0; mt < 2; ++mt) {
                    mma16816(acc[mt][ng][0], ah[mt][0], ah[mt][1], ah[mt][2], ah[mt][3], bh0, bh2);
                    mma16816(acc[mt][ng][1], ah[mt][0], ah[mt][1], ah[mt][2], ah[mt][3], bh1, bh3);
                }
            }
        }

        if (kt < NST - 1) {
            acc_G(WcS, fA, kb0 + (kt + 1) * KC, pd0, pd1);
            sts_A(bufn, fA, tid);
            CP_WAIT0();
        }
        __syncthreads();
    }

    // ---- G write: reduce pd over the 4 threads sharing a row ----
    pd0 += __shfl_xor_sync(0xffffffffu, pd0, 1);
    pd0 += __shfl_xor_sync(0xffffffffu, pd0, 2);
    pd1 += __shfl_xor_sync(0xffffffffu, pd1, 1);
    pd1 += __shfl_xor_sync(0xffffffffu, pd1, 2);
    if ((tid & 3) == 0) {
        const size_t gr = (size_t)(row0 + (tid >> 2)) * 2;
        g_G[gr]     = pd0;
        g_G[gr + 1] = pd1;
    }

    // ---- epilogue ----
    float* Uact = reinterpret_cast<float*>(smem);              // [128][UPAD]
    float* part = reinterpret_cast<float*>(smem) + 128 * UPAD; // [2][128]

    if (cw >= 2) {   // U half: sigma(U + bu) -> Uact
#pragma unroll
        for (int mt = 0; mt < 2; ++mt)
#pragma unroll
            for (int ng = 0; ng < 4; ++ng)
#pragma unroll
                for (int h = 0; h < 2; ++h)
#pragma unroll
                    for (int e = 0; e < 4; ++e) {
                        int r  = rw * 32 + mt * 16 + (lane >> 2) + (e >= 2 ? 8 : 0);
                        int uc = (cw - 2) * 64 + ng * 16 + h * 8 + (lane & 3) * 2 + (e & 1);
                        float x = acc[mt][ng][h][e] + __ldg(&bu[uc]);
                        Uact[r * UPAD + uc] = 1.f / (1.f + expf(-x));
                    }
    }
    __syncthreads();

    if (cw < 2) {    // V half: tanh(V + bv)*Ww * Uact, row-reduce
        float srow[2][2] = {{0.f, 0.f}, {0.f, 0.f}};   // [mt][rhalf]
#pragma unroll
        for (int mt = 0; mt < 2; ++mt)
#pragma unroll
            for (int ng = 0; ng < 4; ++ng)
#pragma unroll
                for (int h = 0; h < 2; ++h)
#pragma unroll
                    for (int e = 0; e < 4; ++e) {
                        int rh = (e >= 2) ? 1 : 0;
                        int r  = rw * 32 + mt * 16 + (lane >> 2) + rh * 8;
                        int c  = cw * 64 + ng * 16 + h * 8 + (lane & 3) * 2 + (e & 1);
                        float x = acc[mt][ng][h][e] + __ldg(&bv[c]);
                        float v = tanhf(x) * __ldg(&Ww[c]);
                        srow[mt][rh] += v * Uact[r * UPAD + c];
                    }
#pragma unroll
        for (int mt = 0; mt < 2; ++mt)
#pragma unroll
            for (int rh = 0; rh < 2; ++rh) {
                srow[mt][rh] += __shfl_xor_sync(0xffffffffu, srow[mt][rh], 1);
                srow[mt][rh] += __shfl_xor_sync(0xffffffffu, srow[mt][rh], 2);
            }
        if ((lane & 3) == 0) {
#pragma unroll
            for (int mt = 0; mt < 2; ++mt)
#pragma unroll
                for (int rh = 0; rh < 2; ++rh) {
                    int r = rw * 32 + mt * 16 + (lane >> 2) + rh * 8;
                    part[cw * 128 + r] = srow[mt][rh];
                }
        }
    }
    __syncthreads();

    if (tid < MT)
        A_pre[(size_t)(row0 + tid)] = part[tid] + part[128 + tid] + bw[0];
}

// ---------------------------------------------------------------------------
// Phase 2+3 merged: per-bag softmax -> A_sftmx, then
// out[b,k] = sum_t a[t]*G[b,t,k] + bc[k]*bias_rel
// ---------------------------------------------------------------------------
__global__ __launch_bounds__(256)
void mil_finish(const float* __restrict__ A_pre,
                const float* __restrict__ bc,
                float* __restrict__ Asm, float* __restrict__ out)
{
    __shared__ float sh0[256];
    __shared__ float sh1[256];
    __shared__ float sh2[256];
    const int b   = blockIdx.x;
    const int tid = threadIdx.x;
    const float* src = A_pre + (size_t)b * T_;

    const int t0 = tid, t1 = tid + 256;
    float v0 = src[t0];
    float v1 = (t1 < T_) ? src[t1] : -INFINITY;

    sh0[tid] = fmaxf(v0, v1);
    __syncthreads();
    for (int s = 128; s > 0; s >>= 1) {
        if (tid < s) sh0[tid] = fmaxf(sh0[tid], sh0[tid + s]);
        __syncthreads();
    }
    const float mx = sh0[0];
    __syncthreads();

    float e0 = expf(v0 - mx);
    float e1 = (t1 < T_) ? expf(v1 - mx) : 0.f;
    sh0[tid] = e0 + e1;
    __syncthreads();
    for (int s = 128; s > 0; s >>= 1) {
        if (tid < s) sh0[tid] += sh0[tid + s];
        __syncthreads();
    }
    const float inv = 1.f / sh0[0];
    __syncthreads();

    const float a0 = e0 * inv;
    const float a1 = e1 * inv;
    Asm[(size_t)b * T_ + t0] = a0;
    if (t1 < T_) Asm[(size_t)b * T_ + t1] = a1;

    const float* Gb = g_G + (size_t)b * T_ * 2;
    float c0 = a0 * Gb[t0 * 2]     + ((t1 < T_) ? a1 * Gb[t1 * 2]     : 0.f);
    float c1 = a0 * Gb[t0 * 2 + 1] + ((t1 < T_) ? a1 * Gb[t1 * 2 + 1] : 0.f);

    sh0[tid] = a0 + a1;   // bias_rel partial
    sh1[tid] = c0;
    sh2[tid] = c1;
    __syncthreads();
    for (int s = 128; s > 0; s >>= 1) {
        if (tid < s) {
            sh0[tid] += sh0[tid + s];
            sh1[tid] += sh1[tid + s];
            sh2[tid] += sh2[tid + s];
        }
        __syncthreads();
    }
    if (tid == 0) {
        const float bias_rel = sh0[0];
        out[(size_t)b * 2 + 0] = sh1[0] + bc[0] * bias_rel;
        out[(size_t)b * 2 + 1] = sh2[0] + bc[1] * bias_rel;
    }
}

// ---------------------------------------------------------------------------
// Launch: d_out = (out[256,2], A_sftmx[256,500], A_pre[256,1,500])
// ---------------------------------------------------------------------------
extern "C" void kernel_launch(void* const* d_in, const int* in_sizes, int n_in,
                              void* d_out, int out_size)
{
    const float* H  = (const float*)d_in[0];
    const float* Wv = (const float*)d_in[1];
    const float* bv = (const float*)d_in[2];
    const float* Wu = (const float*)d_in[3];
    const float* bu = (const float*)d_in[4];
    const float* Ww = (const float*)d_in[5];
    const float* bw = (const float*)d_in[6];
    const float* Wc = (const float*)d_in[7];
    const float* bc = (const float*)d_in[8];

    float* out   = (float*)d_out;               // [256,2]
    float* A_sm  = out + (size_t)B_ * 2;        // [256,500]
    float* A_pre = A_sm + (size_t)B_ * T_;      // [256,1,500]

    // one-time, non-stream host config (no-op during graph capture replays)
    static bool configured = false;
    if (!configured) {
        cudaFuncSetAttribute(mil_phase1_mma,
                             cudaFuncAttributeMaxDynamicSharedMemorySize, SMEM_P1);
        configured = true;
    }

    wsplit_kernel<<<(NN * M_) / 256, 256>>>(Wv, Wu);
    mil_phase1_mma<<<NROWS / MT, NTH, SMEM_P1>>>(H, bv, bu, Ww, bw, Wc, A_pre);
    mil_finish<<<B_, 256>>>(A_pre, bc, A_sm, out);
}